// round 1
// baseline (speedup 1.0000x reference)
#include <cuda_runtime.h>

// ---------------------------------------------------------------------------
// Problem constants: B=64, N=1024, DIN=64, DH=128, H_MLP=128, L=3, C=4
// Layout strategy: h kept node-major as H[N, B*D] (row i = node, col = b*D+d).
// This makes U^T@h and U@m big GEMMs, and the per-(b,i) MLP is just the flat
// reinterpretation [N*B, D] of the same buffer. No transposes after the first.
// ---------------------------------------------------------------------------

#define BM 128
#define BN 128
#define BK 16

// Scratch (static device globals -- allocation-free per harness rules)
__device__ float g_H0[8388608];          // [1024, 8192] (layer0 uses [1024,4096])
__device__ float g_H1[8388608];
__device__ float g_AGG[3 * 8388608];     // per-branch stride 8388608
__device__ float g_M1[3 * 8388608];
__device__ float g_M2[3 * 8388608];
__device__ float g_pooled[64 * 128];

__device__ __forceinline__ float* resolve_buf(int tag, float* ext) {
    switch (tag) {
        case 0: return g_H0;
        case 1: return g_H1;
        case 2: return g_AGG;
        case 3: return g_M1;
        case 4: return g_M2;
        default: return ext;
    }
}

// ---------------------------------------------------------------------------
// Generic SGEMM: C = epi( A(^T) @ B )
//   grid.x tiles Ncols, grid.y tiles M, grid.z = branch (applies strides)
//   epilogue: v = alpha*(acc + bias[col]); if(beta) v += C_old; if(relu) max(0,v)
//   alpha = softmax(bw[bwL])[z] when bwPtr != null, else 1
// ---------------------------------------------------------------------------
__global__ void __launch_bounds__(256)
sgemm_kernel(int tagA, const float* __restrict__ extA, long long offA, long long strideA, int lda,
             int tagB, const float* __restrict__ extB, long long offB, long long strideB, int ldb,
             int tagC, float* extC, long long offC, long long strideC, int ldc,
             int K,
             const float* __restrict__ bias, int strideBias,
             const float* __restrict__ bwPtr, int bwL,
             int transA, int reluFlag, int betaFlag)
{
    __shared__ float As[BK][BM];
    __shared__ float Bs[BK][BN];

    const int z = blockIdx.z;
    const float* A = resolve_buf(tagA, const_cast<float*>(extA)) + offA + (long long)z * strideA;
    const float* B = resolve_buf(tagB, const_cast<float*>(extB)) + offB + (long long)z * strideB;
    float*       C = resolve_buf(tagC, extC) + offC + (long long)z * strideC;
    if (bias) bias += z * strideBias;

    const int bx = blockIdx.x;
    const int by = blockIdx.y;
    const int tid = threadIdx.x;

    const int trow = tid >> 4;            // 0..15 : output row group
    const int tcol = tid & 15;            // 0..15 : output col group

    const int ldRow  = tid >> 5;          // 0..7
    const int ldCol4 = (tid & 31) << 2;   // 0..124

    const int aRowN  = tid >> 2;          // 0..63 (normal-A loader)
    const int aCol4  = (tid & 3) << 2;    // 0,4,8,12

    float acc[8][8];
#pragma unroll
    for (int i = 0; i < 8; i++)
#pragma unroll
        for (int j = 0; j < 8; j++) acc[i][j] = 0.f;

    for (int k0 = 0; k0 < K; k0 += BK) {
        // ---- load B tile: BK x BN, coalesced float4 ----
#pragma unroll
        for (int r = 0; r < BK; r += 8) {
            const float4 v = *reinterpret_cast<const float4*>(
                B + (size_t)(k0 + ldRow + r) * ldb + (size_t)bx * BN + ldCol4);
            *reinterpret_cast<float4*>(&Bs[ldRow + r][ldCol4]) = v;
        }
        // ---- load A tile ----
        if (transA) {
            // A stored [K, M]: same pattern as B
#pragma unroll
            for (int r = 0; r < BK; r += 8) {
                const float4 v = *reinterpret_cast<const float4*>(
                    A + (size_t)(k0 + ldRow + r) * lda + (size_t)by * BM + ldCol4);
                *reinterpret_cast<float4*>(&As[ldRow + r][ldCol4]) = v;
            }
        } else {
            // A stored [M, K]: read rows, transpose into As
#pragma unroll
            for (int r = 0; r < 2; r++) {
                const int m = aRowN + r * 64;
                const float4 v = *reinterpret_cast<const float4*>(
                    A + (size_t)(by * BM + m) * lda + k0 + aCol4);
                As[aCol4 + 0][m] = v.x;
                As[aCol4 + 1][m] = v.y;
                As[aCol4 + 2][m] = v.z;
                As[aCol4 + 3][m] = v.w;
            }
        }
        __syncthreads();

#pragma unroll
        for (int kk = 0; kk < BK; kk++) {
            float ar[8], br[8];
            *reinterpret_cast<float4*>(&ar[0]) = *reinterpret_cast<const float4*>(&As[kk][trow * 8]);
            *reinterpret_cast<float4*>(&ar[4]) = *reinterpret_cast<const float4*>(&As[kk][trow * 8 + 4]);
            *reinterpret_cast<float4*>(&br[0]) = *reinterpret_cast<const float4*>(&Bs[kk][tcol * 8]);
            *reinterpret_cast<float4*>(&br[4]) = *reinterpret_cast<const float4*>(&Bs[kk][tcol * 8 + 4]);
#pragma unroll
            for (int i = 0; i < 8; i++)
#pragma unroll
                for (int j = 0; j < 8; j++)
                    acc[i][j] = fmaf(ar[i], br[j], acc[i][j]);
        }
        __syncthreads();
    }

    // branch mixing weight (softmax over the 3 branch logits of layer bwL)
    float alpha = 1.f;
    if (bwPtr) {
        const float w0 = bwPtr[bwL * 3 + 0];
        const float w1 = bwPtr[bwL * 3 + 1];
        const float w2 = bwPtr[bwL * 3 + 2];
        const float mx = fmaxf(w0, fmaxf(w1, w2));
        const float e0 = expf(w0 - mx), e1 = expf(w1 - mx), e2 = expf(w2 - mx);
        const float inv = 1.f / (e0 + e1 + e2);
        alpha = (z == 0 ? e0 : (z == 1 ? e1 : e2)) * inv;
    }

#pragma unroll
    for (int i = 0; i < 8; i++) {
        const int row = by * BM + trow * 8 + i;
#pragma unroll
        for (int jq = 0; jq < 2; jq++) {
            const int col = bx * BN + tcol * 8 + jq * 4;
            float4 v;
            v.x = acc[i][jq * 4 + 0];
            v.y = acc[i][jq * 4 + 1];
            v.z = acc[i][jq * 4 + 2];
            v.w = acc[i][jq * 4 + 3];
            if (bias) {
                const float4 bv = *reinterpret_cast<const float4*>(bias + col);
                v.x += bv.x; v.y += bv.y; v.z += bv.z; v.w += bv.w;
            }
            v.x *= alpha; v.y *= alpha; v.z *= alpha; v.w *= alpha;
            float4* cp = reinterpret_cast<float4*>(C + (size_t)row * ldc + col);
            if (betaFlag) {
                const float4 o = *cp;
                v.x += o.x; v.y += o.y; v.z += o.z; v.w += o.w;
            }
            if (reluFlag) {
                v.x = fmaxf(v.x, 0.f); v.y = fmaxf(v.y, 0.f);
                v.z = fmaxf(v.z, 0.f); v.w = fmaxf(v.w, 0.f);
            }
            *cp = v;
        }
    }
}

// x[b, j, d] (B=64,N=1024,D=64)  ->  g_H0[j, b*64 + d]   ([1024, 4096])
__global__ void transpose_x_kernel(const float* __restrict__ x)
{
    const int idx = blockIdx.x * 256 + threadIdx.x;   // 4194304 total
    const int d = idx & 63;
    const int b = (idx >> 6) & 63;
    const int j = idx >> 12;
    g_H0[idx] = x[(size_t)b * 65536 + (size_t)j * 64 + d];
}

// pooled[b, d] = mean_i g_H1[i, b*128 + d]
__global__ void pool_kernel()
{
    const int b = blockIdx.x;           // 64 blocks
    const int t = threadIdx.x;          // 512 threads
    const int d = t & 127;
    const int s = t >> 7;               // 0..3
    float sum = 0.f;
    for (int i = s; i < 1024; i += 4)
        sum += g_H1[(size_t)i * 8192 + b * 128 + d];
    __shared__ float red[512];
    red[t] = sum;
    __syncthreads();
    if (s == 0)
        g_pooled[b * 128 + d] =
            (red[d] + red[d + 128] + red[d + 256] + red[d + 384]) * (1.f / 1024.f);
}

// z = PReLU(pooled @ Wc1 + bc1); out = z @ Wc2 + bc2   -> [64, 4]
__global__ void classifier_kernel(const float* __restrict__ Wc1,
                                  const float* __restrict__ bc1,
                                  const float* __restrict__ al,
                                  const float* __restrict__ Wc2,
                                  const float* __restrict__ bc2,
                                  float* __restrict__ out)
{
    __shared__ float zs[64][128];
    const int t = threadIdx.x;          // 256 threads
    for (int idx = t; idx < 64 * 128; idx += 256) {
        const int b = idx >> 7, h = idx & 127;
        float acc = bc1[h];
        for (int d = 0; d < 128; d++)
            acc = fmaf(g_pooled[b * 128 + d], Wc1[d * 128 + h], acc);
        zs[b][h] = acc > 0.f ? acc : al[h] * acc;
    }
    __syncthreads();
    {
        const int b = t >> 2, c = t & 3;
        float acc = bc2[c];
        for (int h = 0; h < 128; h++)
            acc = fmaf(zs[b][h], Wc2[h * 4 + c], acc);
        out[b * 4 + c] = acc;
    }
}

// ---------------------------------------------------------------------------
extern "C" void kernel_launch(void* const* d_in, const int* in_sizes, int n_in,
                              void* d_out, int out_size)
{
    const float* x    = (const float*)d_in[0];
    const float* U    = (const float*)d_in[1];
    const float* w1_0 = (const float*)d_in[2];
    const float* b1_0 = (const float*)d_in[3];
    const float* w2_0 = (const float*)d_in[4];
    const float* b2_0 = (const float*)d_in[5];
    const float* w1_r = (const float*)d_in[6];
    const float* b1_r = (const float*)d_in[7];
    const float* w2_r = (const float*)d_in[8];
    const float* b2_r = (const float*)d_in[9];
    const float* bw   = (const float*)d_in[10];
    const float* Wc1  = (const float*)d_in[11];
    const float* bc1  = (const float*)d_in[12];
    const float* alp  = (const float*)d_in[13];
    const float* Wc2  = (const float*)d_in[14];
    const float* bc2  = (const float*)d_in[15];
    float* out = (float*)d_out;

    const long long SB = 8388608LL;      // per-branch scratch stride (floats)
    const long long UN = 1048576LL;      // per-branch U stride (1024*1024)

    // x -> H0 (node-major)
    transpose_x_kernel<<<16384, 256>>>(x);

    int hinTag = 0, houtTag = 1;
    for (int l = 0; l < 3; l++) {
        const int Din   = (l == 0) ? 64 : 128;
        const int Wcols = 64 * Din;                      // B * Din
        const float* w1 = (l == 0) ? w1_0 : (w1_r + (size_t)(l - 1) * 3 * 128 * 128);
        const float* b1 = (l == 0) ? b1_0 : (b1_r + (size_t)(l - 1) * 3 * 128);
        const float* w2 = (l == 0) ? w2_0 : (w2_r + (size_t)(l - 1) * 3 * 128 * 128);
        const float* b2 = (l == 0) ? b2_0 : (b2_r + (size_t)(l - 1) * 3 * 128);
        const long long sW1 = (l == 0) ? 8192LL : 16384LL;   // w1 per-branch stride

        // 1) AGG_k = U_k^T @ H_in    (M=1024, Nc=Wcols, K=1024), 3 branches in z
        {
            dim3 g(Wcols / BN, 1024 / BM, 3);
            sgemm_kernel<<<g, 256>>>(
                -1, U, 0, UN, 1024,            // A = U_k (trans), lda=1024
                hinTag, nullptr, 0, 0, Wcols,  // B = H_in, shared across z
                2, nullptr, 0, SB, Wcols,      // C = AGG_k
                1024,
                nullptr, 0, nullptr, 0,
                /*transA*/1, /*relu*/0, /*beta*/0);
        }
        // 2) M1_k = relu(AGG_k @ w1_k + b1_k)   (M=65536, Nc=128, K=Din)
        {
            dim3 g(1, 65536 / BM, 3);
            sgemm_kernel<<<g, 256>>>(
                2, nullptr, 0, SB, Din,
                -1, w1, 0, sW1, 128,
                3, nullptr, 0, SB, 128,
                Din,
                b1, 128, nullptr, 0,
                0, /*relu*/1, 0);
        }
        // 3) M2s_k = ws_k * (M1_k @ w2_k + b2_k)   (M=65536, Nc=128, K=128)
        {
            dim3 g(1, 65536 / BM, 3);
            sgemm_kernel<<<g, 256>>>(
                3, nullptr, 0, SB, 128,
                -1, w2, 0, 16384LL, 128,
                4, nullptr, 0, SB, 128,
                128,
                b2, 128, bw, l,
                0, 0, 0);
        }
        // 4) H_out = relu( sum_k U_k @ M2s_k )   (M=1024, Nc=8192, K=1024)
        for (int k = 0; k < 3; k++) {
            dim3 g(8192 / BN, 1024 / BM, 1);
            sgemm_kernel<<<g, 256>>>(
                -1, U + (size_t)k * UN, 0, 0, 1024,
                4, nullptr, (long long)k * SB, 0, 8192,
                houtTag, nullptr, 0, 0, 8192,
                1024,
                nullptr, 0, nullptr, 0,
                0, /*relu*/(k == 2) ? 1 : 0, /*beta*/(k > 0) ? 1 : 0);
        }
        const int t = hinTag; hinTag = houtTag; houtTag = t;
    }

    // final H lives in g_H1 (fixed schedule: out tags 1,0,1)
    pool_kernel<<<64, 512>>>();
    classifier_kernel<<<1, 256>>>(Wc1, bc1, alp, Wc2, bc2, out);
}

// round 2
// speedup vs baseline: 1.1873x; 1.1873x over previous
#include <cuda_runtime.h>
#include <cstdint>

// ---------------------------------------------------------------------------
// B=64, N=1024, DIN=64, DH=128, H_MLP=128, L=3, C=4
// H kept node-major: H[N, B*D]. All heavy ops are GEMMs.
// This round: 3xTF32 tensor-core GEMM (mma.sync.m16n8k8) with exact hi/lo
// split -> fp32-class accuracy on tensor cores.
// ---------------------------------------------------------------------------

#define BM 128
#define BN 128
#define BK 16
#define SW (BM + 8)   // padded smem row (conflict-free quad-row frag loads)

// Scratch (static device globals -- allocation-free per harness rules)
__device__ float g_H0[8388608];          // [1024, 8192] (layer0 uses [1024,4096])
__device__ float g_H1[8388608];
__device__ float g_AGG[3 * 8388608];
__device__ float g_M1[3 * 8388608];
__device__ float g_M2[3 * 8388608];
__device__ float g_pooled[64 * 128];

__device__ __forceinline__ float* resolve_buf(int tag, float* ext) {
    switch (tag) {
        case 0: return g_H0;
        case 1: return g_H1;
        case 2: return g_AGG;
        case 3: return g_M1;
        case 4: return g_M2;
        default: return ext;
    }
}

__device__ __forceinline__ void tf32_split(float x, uint32_t& hi, uint32_t& lo) {
    uint32_t h;
    asm("cvt.rna.tf32.f32 %0, %1;" : "=r"(h) : "f"(x));
    hi = h;
    float l = x - __uint_as_float(h);   // exact (Dekker split)
    uint32_t lr;
    asm("cvt.rna.tf32.f32 %0, %1;" : "=r"(lr) : "f"(l));
    lo = lr;
}

#define MMA_TF32(d, a0, a1, a2, a3, b0, b1)                                          \
    asm volatile(                                                                    \
        "mma.sync.aligned.m16n8k8.row.col.f32.tf32.tf32.f32 "                        \
        "{%0,%1,%2,%3},{%4,%5,%6,%7},{%8,%9},{%0,%1,%2,%3};"                         \
        : "+f"(d[0]), "+f"(d[1]), "+f"(d[2]), "+f"(d[3])                             \
        : "r"(a0), "r"(a1), "r"(a2), "r"(a3), "r"(b0), "r"(b1))

// ---------------------------------------------------------------------------
// GEMM: C = epi( A(^T) @ B ), 3xTF32 tensor cores.
//   grid.x tiles Ncols, grid.y tiles M, grid.z = branch (applies strides)
//   epilogue: v = alpha*(acc + bias[col]); if(beta) v += C_old; if(relu) max(0,v)
// ---------------------------------------------------------------------------
__global__ void __launch_bounds__(256, 1)
gemm3t_kernel(int tagA, const float* __restrict__ extA, long long offA, long long strideA, int lda,
              int tagB, const float* __restrict__ extB, long long offB, long long strideB, int ldb,
              int tagC, float* extC, long long offC, long long strideC, int ldc,
              int K,
              const float* __restrict__ bias, int strideBias,
              const float* __restrict__ bwPtr, int bwL,
              int transA, int reluFlag, int betaFlag)
{
    __shared__ float As[2][BK][SW];
    __shared__ float Bs[2][BK][SW];

    const int z = blockIdx.z;
    const float* A = resolve_buf(tagA, const_cast<float*>(extA)) + offA + (long long)z * strideA;
    const float* B = resolve_buf(tagB, const_cast<float*>(extB)) + offB + (long long)z * strideB;
    float*       C = resolve_buf(tagC, extC) + offC + (long long)z * strideC;
    if (bias) bias += z * strideBias;

    const int bx = blockIdx.x;
    const int by = blockIdx.y;
    const int tid = threadIdx.x;
    const int warp = tid >> 5;
    const int lane = tid & 31;

    const int warpM = (warp >> 2) * 64;   // 2 warp rows
    const int warpN = (warp & 3) * 32;    // 4 warp cols
    const int lr = lane & 3;              // k within quad
    const int lc = lane >> 2;             // 0..7

    // loader indices
    const int ldRow  = tid >> 5;          // 0..7
    const int ldCol4 = (tid & 31) << 2;   // 0..124
    const int aRowN  = tid >> 2;          // 0..63
    const int aCol4  = (tid & 3) << 2;    // 0,4,8,12

    float acc[4][4][4];
#pragma unroll
    for (int i = 0; i < 4; i++)
#pragma unroll
        for (int j = 0; j < 4; j++)
#pragma unroll
            for (int r = 0; r < 4; r++) acc[i][j][r] = 0.f;

    float4 rA[2], rB[2];

    // ---- gmem -> regs ----
    auto load_gmem = [&](int k0) {
        rB[0] = *reinterpret_cast<const float4*>(
            B + (size_t)(k0 + ldRow) * ldb + (size_t)bx * BN + ldCol4);
        rB[1] = *reinterpret_cast<const float4*>(
            B + (size_t)(k0 + ldRow + 8) * ldb + (size_t)bx * BN + ldCol4);
        if (transA) {
            rA[0] = *reinterpret_cast<const float4*>(
                A + (size_t)(k0 + ldRow) * lda + (size_t)by * BM + ldCol4);
            rA[1] = *reinterpret_cast<const float4*>(
                A + (size_t)(k0 + ldRow + 8) * lda + (size_t)by * BM + ldCol4);
        } else {
            rA[0] = *reinterpret_cast<const float4*>(
                A + (size_t)(by * BM + aRowN) * lda + k0 + aCol4);
            rA[1] = *reinterpret_cast<const float4*>(
                A + (size_t)(by * BM + aRowN + 64) * lda + k0 + aCol4);
        }
    };
    // ---- regs -> smem ----
    auto store_smem = [&](int st) {
        *reinterpret_cast<float4*>(&Bs[st][ldRow][ldCol4])     = rB[0];
        *reinterpret_cast<float4*>(&Bs[st][ldRow + 8][ldCol4]) = rB[1];
        if (transA) {
            *reinterpret_cast<float4*>(&As[st][ldRow][ldCol4])     = rA[0];
            *reinterpret_cast<float4*>(&As[st][ldRow + 8][ldCol4]) = rA[1];
        } else {
            const float* p0 = reinterpret_cast<const float*>(&rA[0]);
            const float* p1 = reinterpret_cast<const float*>(&rA[1]);
#pragma unroll
            for (int q = 0; q < 4; q++) {
                As[st][aCol4 + q][aRowN]      = p0[q];
                As[st][aCol4 + q][aRowN + 64] = p1[q];
            }
        }
    };

    load_gmem(0);
    store_smem(0);
    __syncthreads();

    int cur = 0;
    for (int k0 = 0; k0 < K; k0 += BK) {
        const bool hasNext = (k0 + BK < K);
        if (hasNext) load_gmem(k0 + BK);

        // ---- compute from stage cur: two k-steps of 8 ----
#pragma unroll
        for (int ks = 0; ks < 2; ks++) {
            const int kk = ks * 8;
            uint32_t ahi[4][4], alo[4][4];
#pragma unroll
            for (int i = 0; i < 4; i++) {
                const int m0 = warpM + i * 16;
                tf32_split(As[cur][kk + lr][m0 + lc],         ahi[i][0], alo[i][0]);
                tf32_split(As[cur][kk + lr][m0 + 8 + lc],     ahi[i][1], alo[i][1]);
                tf32_split(As[cur][kk + 4 + lr][m0 + lc],     ahi[i][2], alo[i][2]);
                tf32_split(As[cur][kk + 4 + lr][m0 + 8 + lc], ahi[i][3], alo[i][3]);
            }
            uint32_t bhi[4][2], blo[4][2];
#pragma unroll
            for (int j = 0; j < 4; j++) {
                const int n0 = warpN + j * 8;
                tf32_split(Bs[cur][kk + lr][n0 + lc],     bhi[j][0], blo[j][0]);
                tf32_split(Bs[cur][kk + 4 + lr][n0 + lc], bhi[j][1], blo[j][1]);
            }
#pragma unroll
            for (int i = 0; i < 4; i++)
#pragma unroll
                for (int j = 0; j < 4; j++) {
                    MMA_TF32(acc[i][j], ahi[i][0], ahi[i][1], ahi[i][2], ahi[i][3],
                             bhi[j][0], bhi[j][1]);
                    MMA_TF32(acc[i][j], alo[i][0], alo[i][1], alo[i][2], alo[i][3],
                             bhi[j][0], bhi[j][1]);
                    MMA_TF32(acc[i][j], ahi[i][0], ahi[i][1], ahi[i][2], ahi[i][3],
                             blo[j][0], blo[j][1]);
                }
        }

        if (hasNext) {
            store_smem(cur ^ 1);
            __syncthreads();
            cur ^= 1;
        }
    }

    // ---- branch mixing weight ----
    float alpha = 1.f;
    if (bwPtr) {
        const float w0 = bwPtr[bwL * 3 + 0];
        const float w1 = bwPtr[bwL * 3 + 1];
        const float w2 = bwPtr[bwL * 3 + 2];
        const float mx = fmaxf(w0, fmaxf(w1, w2));
        const float e0 = expf(w0 - mx), e1 = expf(w1 - mx), e2 = expf(w2 - mx);
        const float inv = 1.f / (e0 + e1 + e2);
        alpha = (z == 0 ? e0 : (z == 1 ? e1 : e2)) * inv;
    }

    // ---- epilogue: fragment layout writes (float2) ----
#pragma unroll
    for (int i = 0; i < 4; i++) {
        const int row0 = by * BM + warpM + i * 16 + lc;
        const int row1 = row0 + 8;
#pragma unroll
        for (int j = 0; j < 4; j++) {
            const int col = bx * BN + warpN + j * 8 + lr * 2;
            float2 bv = make_float2(0.f, 0.f);
            if (bias) bv = *reinterpret_cast<const float2*>(bias + col);

            float2 v0, v1;
            v0.x = (acc[i][j][0] + bv.x) * alpha;
            v0.y = (acc[i][j][1] + bv.y) * alpha;
            v1.x = (acc[i][j][2] + bv.x) * alpha;
            v1.y = (acc[i][j][3] + bv.y) * alpha;

            float2* cp0 = reinterpret_cast<float2*>(C + (size_t)row0 * ldc + col);
            float2* cp1 = reinterpret_cast<float2*>(C + (size_t)row1 * ldc + col);
            if (betaFlag) {
                const float2 o0 = *cp0, o1 = *cp1;
                v0.x += o0.x; v0.y += o0.y;
                v1.x += o1.x; v1.y += o1.y;
            }
            if (reluFlag) {
                v0.x = fmaxf(v0.x, 0.f); v0.y = fmaxf(v0.y, 0.f);
                v1.x = fmaxf(v1.x, 0.f); v1.y = fmaxf(v1.y, 0.f);
            }
            *cp0 = v0;
            *cp1 = v1;
        }
    }
}

// x[b, j, d] (B=64,N=1024,D=64)  ->  g_H0[j, b*64 + d]   ([1024, 4096])
__global__ void transpose_x_kernel(const float* __restrict__ x)
{
    const int idx = blockIdx.x * 256 + threadIdx.x;
    const int d = idx & 63;
    const int b = (idx >> 6) & 63;
    const int j = idx >> 12;
    g_H0[idx] = x[(size_t)b * 65536 + (size_t)j * 64 + d];
}

// pooled[b, d] = mean_i g_H1[i, b*128 + d]
__global__ void pool_kernel()
{
    const int b = blockIdx.x;
    const int t = threadIdx.x;
    const int d = t & 127;
    const int s = t >> 7;
    float sum = 0.f;
    for (int i = s; i < 1024; i += 4)
        sum += g_H1[(size_t)i * 8192 + b * 128 + d];
    __shared__ float red[512];
    red[t] = sum;
    __syncthreads();
    if (s == 0)
        g_pooled[b * 128 + d] =
            (red[d] + red[d + 128] + red[d + 256] + red[d + 384]) * (1.f / 1024.f);
}

// z = PReLU(pooled @ Wc1 + bc1); out = z @ Wc2 + bc2   -> [64, 4]
__global__ void classifier_kernel(const float* __restrict__ Wc1,
                                  const float* __restrict__ bc1,
                                  const float* __restrict__ al,
                                  const float* __restrict__ Wc2,
                                  const float* __restrict__ bc2,
                                  float* __restrict__ out)
{
    __shared__ float zs[64][128];
    const int t = threadIdx.x;
    for (int idx = t; idx < 64 * 128; idx += 256) {
        const int b = idx >> 7, h = idx & 127;
        float acc = bc1[h];
        for (int d = 0; d < 128; d++)
            acc = fmaf(g_pooled[b * 128 + d], Wc1[d * 128 + h], acc);
        zs[b][h] = acc > 0.f ? acc : al[h] * acc;
    }
    __syncthreads();
    {
        const int b = t >> 2, c = t & 3;
        float acc = bc2[c];
        for (int h = 0; h < 128; h++)
            acc = fmaf(zs[b][h], Wc2[h * 4 + c], acc);
        out[b * 4 + c] = acc;
    }
}

// ---------------------------------------------------------------------------
extern "C" void kernel_launch(void* const* d_in, const int* in_sizes, int n_in,
                              void* d_out, int out_size)
{
    const float* x    = (const float*)d_in[0];
    const float* U    = (const float*)d_in[1];
    const float* w1_0 = (const float*)d_in[2];
    const float* b1_0 = (const float*)d_in[3];
    const float* w2_0 = (const float*)d_in[4];
    const float* b2_0 = (const float*)d_in[5];
    const float* w1_r = (const float*)d_in[6];
    const float* b1_r = (const float*)d_in[7];
    const float* w2_r = (const float*)d_in[8];
    const float* b2_r = (const float*)d_in[9];
    const float* bw   = (const float*)d_in[10];
    const float* Wc1  = (const float*)d_in[11];
    const float* bc1  = (const float*)d_in[12];
    const float* alp  = (const float*)d_in[13];
    const float* Wc2  = (const float*)d_in[14];
    const float* bc2  = (const float*)d_in[15];
    float* out = (float*)d_out;

    const long long SB = 8388608LL;
    const long long UN = 1048576LL;

    transpose_x_kernel<<<16384, 256>>>(x);

    int hinTag = 0, houtTag = 1;
    for (int l = 0; l < 3; l++) {
        const int Din   = (l == 0) ? 64 : 128;
        const int Wcols = 64 * Din;
        const float* w1 = (l == 0) ? w1_0 : (w1_r + (size_t)(l - 1) * 3 * 128 * 128);
        const float* b1 = (l == 0) ? b1_0 : (b1_r + (size_t)(l - 1) * 3 * 128);
        const float* w2 = (l == 0) ? w2_0 : (w2_r + (size_t)(l - 1) * 3 * 128 * 128);
        const float* b2 = (l == 0) ? b2_0 : (b2_r + (size_t)(l - 1) * 3 * 128);
        const long long sW1 = (l == 0) ? 8192LL : 16384LL;

        // 1) AGG_k = U_k^T @ H_in
        {
            dim3 g(Wcols / BN, 1024 / BM, 3);
            gemm3t_kernel<<<g, 256>>>(
                -1, U, 0, UN, 1024,
                hinTag, nullptr, 0, 0, Wcols,
                2, nullptr, 0, SB, Wcols,
                1024,
                nullptr, 0, nullptr, 0,
                1, 0, 0);
        }
        // 2) M1_k = relu(AGG_k @ w1_k + b1_k)
        {
            dim3 g(1, 65536 / BM, 3);
            gemm3t_kernel<<<g, 256>>>(
                2, nullptr, 0, SB, Din,
                -1, w1, 0, sW1, 128,
                3, nullptr, 0, SB, 128,
                Din,
                b1, 128, nullptr, 0,
                0, 1, 0);
        }
        // 3) M2s_k = ws_k * (M1_k @ w2_k + b2_k)
        {
            dim3 g(1, 65536 / BM, 3);
            gemm3t_kernel<<<g, 256>>>(
                3, nullptr, 0, SB, 128,
                -1, w2, 0, 16384LL, 128,
                4, nullptr, 0, SB, 128,
                128,
                b2, 128, bw, l,
                0, 0, 0);
        }
        // 4) H_out = relu( sum_k U_k @ M2s_k )
        for (int k = 0; k < 3; k++) {
            dim3 g(8192 / BN, 1024 / BM, 1);
            gemm3t_kernel<<<g, 256>>>(
                -1, U + (size_t)k * UN, 0, 0, 1024,
                4, nullptr, (long long)k * SB, 0, 8192,
                houtTag, nullptr, 0, 0, 8192,
                1024,
                nullptr, 0, nullptr, 0,
                0, (k == 2) ? 1 : 0, (k > 0) ? 1 : 0);
        }
        const int t = hinTag; hinTag = houtTag; houtTag = t;
    }

    pool_kernel<<<64, 512>>>();
    classifier_kernel<<<1, 256>>>(Wc1, bc1, alp, Wc2, bc2, out);
}